// round 1
// baseline (speedup 1.0000x reference)
#include <cuda_runtime.h>
#include <cstdint>
#include <cstdio>

#define N_INS 8192
#define T_MAX 16
#define HID   256
#define GATES 1024
#define NCLUS 8

// ---------------- scratch (static device globals; no allocations) ----------
__device__ float g_H[N_INS * HID];        // 8 MB  hidden state / ins_embeds
__device__ float g_C[N_INS * HID];        // 8 MB  cell state
__device__ float g_G[N_INS * GATES];      // 32 MB gate pre-activations / precomputed x@Wih_i
__device__ float g_part[NCLUS * N_INS];   // per-cluster-CTA output partials

__device__ __forceinline__ float sigmoidf_(float x) {
    return 1.0f / (1.0f + expf(-x));
}

// ---------------------------------------------------------------------------
// Dual-source GEMM:  Cmat[m, n] = sum_k A1[m,k]*W1[n,k] (k<K1)
//                              + sum_k A2[m,k]*W2[n,k] (k<K2)
// A row-major with row stride lda; W row-major [1024, 256]; Cmat ldc = 1024.
// M=8192 (grid.x*128), N=1024 (grid.y*64). K1,K2 multiples of 16.
// ---------------------------------------------------------------------------
__global__ void __launch_bounds__(256)
gemm_dual(float* __restrict__ Cmat,
          const float* __restrict__ A1, int lda1,
          const float* __restrict__ W1, int K1,
          const float* __restrict__ A2, int lda2,
          const float* __restrict__ W2, int K2)
{
    __shared__ __align__(16) float As[16][132];
    __shared__ __align__(16) float Ws[16][68];

    const int tid = threadIdx.x;
    const int bm  = blockIdx.x * 128;
    const int bn  = blockIdx.y * 64;
    const int tm  = (tid >> 4) * 8;   // 0..120
    const int tn  = (tid & 15) * 4;   // 0..60

    float acc[8][4];
#pragma unroll
    for (int i = 0; i < 8; ++i)
#pragma unroll
        for (int j = 0; j < 4; ++j) acc[i][j] = 0.0f;

    for (int phase = 0; phase < 2; ++phase) {
        const float* A  = phase ? A2 : A1;
        const float* W  = phase ? W2 : W1;
        const int   lda = phase ? lda2 : lda1;
        const int   KK  = phase ? K2 : K1;

        for (int k0 = 0; k0 < KK; k0 += 16) {
            // load A tile [128 x 16] (transposed into As[k][m])
#pragma unroll
            for (int i = 0; i < 2; ++i) {
                int idx = tid + i * 256;
                int m   = idx >> 2;
                int kq  = (idx & 3) << 2;
                const float4 v = *reinterpret_cast<const float4*>(
                    A + (size_t)(bm + m) * lda + (k0 + kq));
                As[kq + 0][m] = v.x;
                As[kq + 1][m] = v.y;
                As[kq + 2][m] = v.z;
                As[kq + 3][m] = v.w;
            }
            // load W tile [64 x 16] (transposed into Ws[k][n])
            {
                int n  = tid >> 2;
                int kq = (tid & 3) << 2;
                const float4 v = *reinterpret_cast<const float4*>(
                    W + (size_t)(bn + n) * 256 + (k0 + kq));
                Ws[kq + 0][n] = v.x;
                Ws[kq + 1][n] = v.y;
                Ws[kq + 2][n] = v.z;
                Ws[kq + 3][n] = v.w;
            }
            __syncthreads();

#pragma unroll
            for (int k = 0; k < 16; ++k) {
                const float4 a0 = *reinterpret_cast<const float4*>(&As[k][tm]);
                const float4 a1 = *reinterpret_cast<const float4*>(&As[k][tm + 4]);
                const float4 wv = *reinterpret_cast<const float4*>(&Ws[k][tn]);
                const float a[8] = {a0.x, a0.y, a0.z, a0.w, a1.x, a1.y, a1.z, a1.w};
                const float w[4] = {wv.x, wv.y, wv.z, wv.w};
#pragma unroll
                for (int i = 0; i < 8; ++i)
#pragma unroll
                    for (int j = 0; j < 4; ++j)
                        acc[i][j] = fmaf(a[i], w[j], acc[i][j]);
            }
            __syncthreads();
        }
    }

#pragma unroll
    for (int i = 0; i < 8; ++i) {
        float4 v = make_float4(acc[i][0], acc[i][1], acc[i][2], acc[i][3]);
        *reinterpret_cast<float4*>(Cmat + (size_t)(bm + tm + i) * GATES + bn + tn) = v;
    }
}

// ---------------------------------------------------------------------------
// Token LSTM pointwise update: given gate pre-activations G (no bias yet),
// update H,C where t < lengths[n].
// ---------------------------------------------------------------------------
__global__ void __launch_bounds__(256)
token_update(const float* __restrict__ G,
             const int* __restrict__ lengths,
             const float* __restrict__ bih,
             const float* __restrict__ bhh,
             int t)
{
    const int idx = blockIdx.x * 256 + threadIdx.x;   // over 8192*256
    const int n = idx >> 8;
    const int j = idx & 255;
    if (t >= lengths[n]) return;

    const size_t base = (size_t)n * GATES;
    const float gi = G[base + j]        + bih[j]        + bhh[j];
    const float gf = G[base + 256 + j]  + bih[256 + j]  + bhh[256 + j];
    const float gg = G[base + 512 + j]  + bih[512 + j]  + bhh[512 + j];
    const float go = G[base + 768 + j]  + bih[768 + j]  + bhh[768 + j];

    float c = g_C[idx];
    c = sigmoidf_(gf) * c + sigmoidf_(gi) * tanhf(gg);
    g_C[idx] = c;
    g_H[idx] = sigmoidf_(go) * tanhf(c);
}

// ---------------------------------------------------------------------------
// Serial instruction LSTM: 8-CTA cluster, 512 thr/CTA.
// CTA owns h-elements [cta*32, cta*32+32) -> 128 rows of Whh_i (4 gates x 32).
// Whh slice lives in registers (64 floats/thread). h broadcast via DSMEM.
// One cluster barrier per step (double-buffered h).
// G = precomputed ins_embeds @ Wih_i^T (bias added here).
// ---------------------------------------------------------------------------
__global__ void __launch_bounds__(512, 1) __cluster_dims__(NCLUS, 1, 1)
ins_lstm(const float* __restrict__ G,
         const float* __restrict__ Whh,
         const float* __restrict__ bih,
         const float* __restrict__ bhh,
         const float* __restrict__ Wl,
         float* __restrict__ part)
{
    // h buffers: 4 chunks of 64 floats, each chunk padded to 68 (bank spread)
    __shared__ __align__(16) float hbuf[2][4 * 68];
    __shared__ float gs[128];
    __shared__ float hn[32];

    const int tid  = threadIdx.x;
    const int cta  = blockIdx.x;          // == cluster rank (grid = 1 cluster)
    const int r    = tid >> 2;            // row within CTA slice, 0..127
    const int q    = tid & 3;             // K-quadrant, 0..3
    const int gate = r >> 5;
    const int e    = r & 31;
    const int grow = gate * 256 + cta * 32 + e;   // global gate row 0..1023

    // weights for this thread: Whh[grow][q*64 .. q*64+63]
    float w[64];
#pragma unroll
    for (int jj = 0; jj < 16; ++jj) {
        const float4 v = *reinterpret_cast<const float4*>(
            Whh + (size_t)grow * 256 + q * 64 + jj * 4);
        w[4 * jj + 0] = v.x; w[4 * jj + 1] = v.y;
        w[4 * jj + 2] = v.z; w[4 * jj + 3] = v.w;
    }
    const float brow = bih[grow] + bhh[grow];

    float cstate = 0.0f;
    float wl = 0.0f;
    if (tid < 32) wl = Wl[cta * 32 + tid];

    for (int i = tid; i < 2 * 4 * 68; i += 512)
        (&hbuf[0][0])[i] = 0.0f;
    __syncthreads();

    int p = 0;
    for (int s = 0; s < N_INS; ++s) {
        // prefetch precomputed x-part of the gate (L2-resident, hidden by dots)
        float gpre = 0.0f;
        if (q == 0) gpre = __ldg(&G[(size_t)s * GATES + grow]);

        const float4* hp =
            reinterpret_cast<const float4*>(&hbuf[p][q * 68]);
        float a0 = 0.f, a1 = 0.f, a2 = 0.f, a3 = 0.f;
#pragma unroll
        for (int jj = 0; jj < 16; ++jj) {
            const float4 hv = hp[jj];
            a0 = fmaf(w[4 * jj + 0], hv.x, a0);
            a1 = fmaf(w[4 * jj + 1], hv.y, a1);
            a2 = fmaf(w[4 * jj + 2], hv.z, a2);
            a3 = fmaf(w[4 * jj + 3], hv.w, a3);
        }
        float acc = (a0 + a1) + (a2 + a3);
        acc += __shfl_xor_sync(0xffffffffu, acc, 1);
        acc += __shfl_xor_sync(0xffffffffu, acc, 2);
        if (q == 0) gs[r] = acc + gpre + brow;
        __syncthreads();

        if (tid < 32) {
            const float gi = gs[tid];
            const float gf = gs[32 + tid];
            const float gg = gs[64 + tid];
            const float go = gs[96 + tid];
            cstate = sigmoidf_(gf) * cstate + sigmoidf_(gi) * tanhf(gg);
            const float h = sigmoidf_(go) * tanhf(cstate);
            hn[tid] = h;
            float pp = h * wl;
#pragma unroll
            for (int o = 16; o > 0; o >>= 1)
                pp += __shfl_xor_sync(0xffffffffu, pp, o);
            if (tid == 0) part[(size_t)cta * N_INS + s] = pp;
        }
        __syncthreads();

        // broadcast this CTA's 32 new h values to every CTA's other buffer
        if (tid < 256) {
            const int peer = tid >> 5;
            const int el   = tid & 31;
            const float v  = hn[el];
            const int vg   = cta * 32 + el;                    // global h index
            const int di   = (vg >> 6) * 68 + (vg & 63);       // padded layout
            uint32_t laddr = (uint32_t)__cvta_generic_to_shared(&hbuf[p ^ 1][di]);
            uint32_t raddr;
            asm volatile("mapa.shared::cluster.u32 %0, %1, %2;"
                         : "=r"(raddr) : "r"(laddr), "r"(peer));
            asm volatile("st.shared::cluster.b32 [%0], %1;"
                         :: "r"(raddr), "r"(__float_as_uint(v)) : "memory");
        }

        // one cluster barrier per step (release/acquire semantics built-in)
        asm volatile("barrier.cluster.arrive.aligned;" ::: "memory");
        asm volatile("barrier.cluster.wait.aligned;" ::: "memory");
        p ^= 1;
    }
}

// ---------------------------------------------------------------------------
__global__ void __launch_bounds__(256)
finalize(float* __restrict__ out, const float* __restrict__ part,
         const float* __restrict__ bl)
{
    const int n = blockIdx.x * 256 + threadIdx.x;
    float s = bl[0];
#pragma unroll
    for (int k = 0; k < NCLUS; ++k) s += part[(size_t)k * N_INS + n];
    out[n] = s;
}

// ---------------------------------------------------------------------------
extern "C" void kernel_launch(void* const* d_in, const int* in_sizes, int n_in,
                              void* d_out, int out_size)
{
    const float* tokens = (const float*)d_in[0];   // [8192,16,256]
    const int*   lengths= (const int*)  d_in[1];   // [8192]
    const float* Wih_t  = (const float*)d_in[2];   // [1024,256]
    const float* Whh_t  = (const float*)d_in[3];   // [1024,256]
    const float* bih_t  = (const float*)d_in[4];
    const float* bhh_t  = (const float*)d_in[5];
    const float* Wih_i  = (const float*)d_in[6];
    const float* Whh_i  = (const float*)d_in[7];
    const float* bih_i  = (const float*)d_in[8];
    const float* bhh_i  = (const float*)d_in[9];
    const float* Wl     = (const float*)d_in[10];  // [1,256]
    const float* bl     = (const float*)d_in[11];  // [1]
    float* out = (float*)d_out;

    float *H, *C, *G, *part;
    cudaGetSymbolAddress((void**)&H,    g_H);
    cudaGetSymbolAddress((void**)&C,    g_C);
    cudaGetSymbolAddress((void**)&G,    g_G);
    cudaGetSymbolAddress((void**)&part, g_part);

    cudaMemsetAsync(H, 0, (size_t)N_INS * HID * sizeof(float));
    cudaMemsetAsync(C, 0, (size_t)N_INS * HID * sizeof(float));

    dim3 gemm_grid(N_INS / 128, GATES / 64);

    // ---- token-level LSTM: 16 steps of GEMM + pointwise ----
    for (int t = 0; t < T_MAX; ++t) {
        gemm_dual<<<gemm_grid, 256>>>(G,
                                      tokens + (size_t)t * HID, T_MAX * HID, Wih_t, HID,
                                      H, HID, Whh_t, HID);
        token_update<<<N_INS, 256>>>(G, lengths, bih_t, bhh_t, t);
    }

    // ---- precompute ins_embeds @ Wih_i^T ----
    gemm_dual<<<gemm_grid, 256>>>(G, H, HID, Wih_i, HID,
                                  nullptr, 0, nullptr, 0);

    // ---- serial instruction-level LSTM (8-CTA cluster) ----
    ins_lstm<<<NCLUS, 512>>>(G, Whh_i, bih_i, bhh_i, Wl, part);

    // ---- output projection finalize ----
    finalize<<<N_INS / 256, 256>>>(out, part, bl);
}